// round 13
// baseline (speedup 1.0000x reference)
#include <cuda_runtime.h>
#include <cuda_bf16.h>
#include <cuda_fp16.h>
#include <cstdint>

// Problem constants
#define BSZ 1024
#define DIM 2048
#define NMEM 16384
#define INV_TEMP 20.0f
#define QSCALE 32.0f
#define INV_QS2 (1.0f / (QSCALE * QSCALE))

// GEMM tiling (fp8). 64x128 tile, 128 threads, KC=128, 2 stages = 48KB -> 4 CTAs/SM.
#define TM 64
#define TN 128
#define KC 128
#define NSTG 2
#define NKIT (DIM / KC)        // 16
#define NB_TILES (NMEM / TN)   // 128
#define STAGE_BYTES ((TM + TN) * KC)    // 24576
#define SMEM_TOTAL (NSTG * STAGE_BYTES) // 49152
#define GTHREADS 128

// ---------------- scratch ----------------
__device__ float    g_Xn [3u * BSZ * DIM];
__device__ uint8_t  g_Xq [3u * BSZ * DIM];
__device__ uint8_t  g_Fq [3u * (size_t)NMEM * DIM];
__device__ float    g_part[3u * 3u * (size_t)BSZ * NB_TILES];  // [pq][row][nbk]
__device__ float    g_stats[3u * BSZ * 3u];
__device__ float    g_ldRow[3u * BSZ];
__device__ float    g_st  [3u * BSZ];

// ---------------- helpers ----------------
__device__ __forceinline__ uint32_t smem_u32(const void* p) {
    uint32_t a;
    asm("{ .reg .u64 t; cvta.to.shared.u64 t, %1; cvt.u32.u64 %0, t; }" : "=r"(a) : "l"(p));
    return a;
}
__device__ __forceinline__ void cp16(uint32_t saddr, const void* g) {
    asm volatile("cp.async.cg.shared.global [%0], [%1], 16;\n" :: "r"(saddr), "l"(g));
}
__device__ __forceinline__ void cp_commit() { asm volatile("cp.async.commit_group;\n" ::: "memory"); }
__device__ __forceinline__ void cp_wait1()  { asm volatile("cp.async.wait_group 1;\n" ::: "memory"); }

__device__ __forceinline__ void ldsm4(uint32_t (&r)[4], uint32_t addr) {
    asm volatile("ldmatrix.sync.aligned.m8n8.x4.shared.b16 {%0,%1,%2,%3}, [%4];"
                 : "=r"(r[0]), "=r"(r[1]), "=r"(r[2]), "=r"(r[3]) : "r"(addr));
}
// FP8 QMMA with FP16 accumulators
__device__ __forceinline__ void mma16832h(uint32_t (&c)[2], const uint32_t (&a)[4],
                                          uint32_t b0, uint32_t b1) {
    asm volatile(
        "mma.sync.aligned.m16n8k32.row.col.f16.e4m3.e4m3.f16 "
        "{%0,%1}, {%2,%3,%4,%5}, {%6,%7}, {%0,%1};\n"
        : "+r"(c[0]), "+r"(c[1])
        : "r"(a[0]), "r"(a[1]), "r"(a[2]), "r"(a[3]), "r"(b0), "r"(b1));
}
__device__ __forceinline__ float sqrt_approx(float x) {
    float r; asm("sqrt.approx.f32 %0, %1;" : "=f"(r) : "f"(x)); return r;
}
__device__ __forceinline__ uint32_t pack_e4m3_4(float a, float b, float c, float d) {
    uint16_t lo, hi;
    asm("cvt.rn.satfinite.e4m3x2.f32 %0, %1, %2;" : "=h"(lo) : "f"(b), "f"(a));
    asm("cvt.rn.satfinite.e4m3x2.f32 %0, %1, %2;" : "=h"(hi) : "f"(d), "f"(c));
    return (uint32_t)lo | ((uint32_t)hi << 16);
}

__device__ __forceinline__ float blockReduceSum(float v, float* sm) {
    const unsigned m = 0xffffffffu;
    #pragma unroll
    for (int o = 16; o; o >>= 1) v += __shfl_down_sync(m, v, o);
    int lane = threadIdx.x & 31, w = threadIdx.x >> 5;
    __syncthreads();
    if (lane == 0) sm[w] = v;
    __syncthreads();
    if (w == 0) {
        int nw = blockDim.x >> 5;
        float r = (lane < nw) ? sm[lane] : 0.0f;
        #pragma unroll
        for (int o = 16; o; o >>= 1) r += __shfl_down_sync(m, r, o);
        if (lane == 0) sm[0] = r;
    }
    __syncthreads();
    return sm[0];
}

// ---------------- probes (keep gemm in ncu's profiled 4th-launch slot) --------
__global__ void probe_kernel() {}
__global__ void probe2_kernel() {}

// ---------------- K1: fused normalize(+quantize) and feature fp32->e4m3 -------
__global__ void prep_kernel(const float* __restrict__ x0, const float* __restrict__ x1,
                            const float* __restrict__ x2, const float* __restrict__ t0,
                            const float* __restrict__ t1, const float* __restrict__ t2,
                            const float* __restrict__ f0, const float* __restrict__ f1,
                            const float* __restrict__ f2) {
    int p = blockIdx.y, tid = threadIdx.x;
    if (blockIdx.x >= 1024) {
        int j = blockIdx.x - 1024;
        const float4* F = (const float4*)(p == 0 ? f0 : (p == 1 ? f1 : f2));
        uint32_t* out = (uint32_t*)(g_Fq + (size_t)p * NMEM * DIM);
        #pragma unroll
        for (int w = 0; w < 32; w++) {
            int i = j * 256 + tid + w * (1024 * 256);
            float4 v = F[i];
            out[i] = pack_e4m3_4(v.x*QSCALE, v.y*QSCALE, v.z*QSCALE, v.w*QSCALE);
        }
        return;
    }
    __shared__ float sm[32];
    int b = blockIdx.x;
    const float* X = (p == 0 ? x0 : (p == 1 ? x1 : x2)) + (size_t)b * DIM;
    const float* T = (p == 0 ? t0 : (p == 1 ? t1 : t2)) + (size_t)b * DIM;
    float xr[8], tr[8], sx = 0.f, st = 0.f;
    #pragma unroll
    for (int gI = 0; gI < 2; gI++) {
        float4 xv = ((const float4*)X)[tid + gI * 256];
        float4 tv = ((const float4*)T)[tid + gI * 256];
        xr[gI*4+0]=xv.x; xr[gI*4+1]=xv.y; xr[gI*4+2]=xv.z; xr[gI*4+3]=xv.w;
        tr[gI*4+0]=tv.x; tr[gI*4+1]=tv.y; tr[gI*4+2]=tv.z; tr[gI*4+3]=tv.w;
        #pragma unroll
        for (int j = 0; j < 4; j++) {
            sx = fmaf(xr[gI*4+j], xr[gI*4+j], sx);
            st = fmaf(tr[gI*4+j], tr[gI*4+j], st);
        }
    }
    sx = blockReduceSum(sx, sm);
    st = blockReduceSum(st, sm);
    float ix = 1.0f / fmaxf(sqrtf(sx), 1e-12f);
    float it = 1.0f / fmaxf(sqrtf(st), 1e-12f);
    float*    out  = g_Xn + ((size_t)p * BSZ + b) * DIM;
    uint32_t* outq = (uint32_t*)(g_Xq + ((size_t)p * BSZ + b) * DIM);
    float ld = 0.f;
    #pragma unroll
    for (int gI = 0; gI < 2; gI++) {
        float xn[4];
        #pragma unroll
        for (int j = 0; j < 4; j++) {
            xn[j] = xr[gI*4+j] * ix;
            float d = xn[j] - tr[gI*4+j] * it;
            ld = fmaf(d, d, ld);
        }
        float4 ov; ov.x = xn[0]; ov.y = xn[1]; ov.z = xn[2]; ov.w = xn[3];
        ((float4*)out)[tid + gI * 256] = ov;
        outq[tid + gI * 256] = pack_e4m3_4(xn[0]*QSCALE, xn[1]*QSCALE, xn[2]*QSCALE, xn[3]*QSCALE);
    }
    ld = blockReduceSum(ld, sm);
    if (tid == 0) g_ldRow[p * BSZ + b] = ld;
}

// ---------------- K2: FP8 QMMA GEMM, 64x128 tile, 128 thr, 4 CTAs/SM ----------
__global__ void __launch_bounds__(GTHREADS, 4) gemm_kernel() {
    extern __shared__ char smem[];
    const uint32_t smem_base = smem_u32(smem);
    const int tid = threadIdx.x;
    const int wid = tid >> 5, lane = tid & 31;
    const int mb = blockIdx.x, nb = blockIdx.y, pair = blockIdx.z;  // mb fastest: co-residents share B
    const uint8_t* A  = g_Xq + ((size_t)pair * BSZ  + (size_t)mb * TM) * DIM;
    const uint8_t* Bm = g_Fq + ((size_t)pair * NMEM + (size_t)nb * TN) * DIM;

    const int wn = wid;                         // 1x4 warp grid; warp tile 64(M) x 32(N)
    const int l15 = lane & 15, hi = lane >> 4;
    const int g = lane >> 2, t = lane & 3;

    // cp.async bases: rA = tid>>3 (0..15), chA = tid&7; 16-row steps keep r&7 -> +2048 imm.
    const uint32_t rA  = (uint32_t)tid >> 3;
    const uint32_t chA = (uint32_t)tid & 7;
    const uint8_t* gA = A  + rA * DIM + chA * 16;
    const uint8_t* gB = Bm + rA * DIM + chA * 16;
    const uint32_t sA0 = (rA << 7) + (((chA ^ (rA & 7))) << 4);

    // ldmatrix bases; addr(ks) = base ^ (ks<<5), ks 0..3; mt/ng step = +2048 (16 rows)
    const uint32_t aBase = ((uint32_t)l15 << 7) + ((((uint32_t)hi ^ (l15 & 7))) << 4);
    const uint32_t rBm = (uint32_t)(wn * 32) + l15;
    const uint32_t bBase = (uint32_t)(TM * KC) + (rBm << 7) + ((((uint32_t)hi ^ (l15 & 7))) << 4);

    uint32_t c[4][4][2];   // f16x2 accumulators: 64(M) x 32(N) per warp
    #pragma unroll
    for (int mt = 0; mt < 4; mt++)
        #pragma unroll
        for (int nt = 0; nt < 4; nt++) { c[mt][nt][0] = 0u; c[mt][nt][1] = 0u; }

    // prologue: both stages (12 cp16/thread per stage: 4 A + 8 B row-steps)
    #pragma unroll
    for (int j = 0; j < 2; j++) {
        uint32_t sb = smem_base + j * STAGE_BYTES;
        #pragma unroll
        for (int w = 0; w < 4; w++)
            cp16(sb + sA0 + w * 2048, gA + j * KC + w * 16 * DIM);
        #pragma unroll
        for (int w = 0; w < 8; w++)
            cp16(sb + TM * KC + sA0 + w * 2048, gB + j * KC + w * 16 * DIM);
        cp_commit();
    }

    uint32_t af[2][4][4], bfr[2][2][4];   // double-buffered fragments
    for (int i = 0; i < NKIT; i++) {
        const uint32_t sb = smem_base + (i & 1) * STAGE_BYTES;
        cp_wait1();
        __syncthreads();
        // ks=0 fragments
        #pragma unroll
        for (int mt = 0; mt < 4; mt++) ldsm4(af[0][mt], sb + aBase + mt * 2048);
        #pragma unroll
        for (int ng = 0; ng < 2; ng++) ldsm4(bfr[0][ng], sb + bBase + ng * 2048);
        #pragma unroll
        for (int ks = 0; ks < 4; ks++) {
            int cur = ks & 1;
            if (ks < 3) {
                uint32_t x = (uint32_t)(ks + 1) << 5;
                #pragma unroll
                for (int mt = 0; mt < 4; mt++) ldsm4(af[cur ^ 1][mt], (sb + aBase + mt * 2048) ^ x);
                #pragma unroll
                for (int ng = 0; ng < 2; ng++) ldsm4(bfr[cur ^ 1][ng], (sb + bBase + ng * 2048) ^ x);
            }
            #pragma unroll
            for (int mt = 0; mt < 4; mt++)
                #pragma unroll
                for (int nt = 0; nt < 4; nt++) {
                    int ng = nt >> 1, od = nt & 1;
                    mma16832h(c[mt][nt], af[cur][mt], bfr[cur][ng][od], bfr[cur][ng][od + 2]);
                }
        }
        __syncthreads();  // stage fully consumed before overwrite
        if (i + NSTG < NKIT) {
            int k0 = (i + NSTG) * KC;
            #pragma unroll
            for (int w = 0; w < 4; w++)
                cp16(sb + sA0 + w * 2048, gA + k0 + w * 16 * DIM);
            #pragma unroll
            for (int w = 0; w < 8; w++)
                cp16(sb + TM * KC + sA0 + w * 2048, gB + k0 + w * 16 * DIM);
        }
        cp_commit();   // (possibly empty) group keeps wait arithmetic uniform
    }

    // ---- fused epilogue: per-row partials ZL, ZD, ZD2 ----
    float zl[8], zd[8], zq[8];   // k = mt*2 + h
    #pragma unroll
    for (int k = 0; k < 8; k++) { zl[k] = 0.f; zd[k] = 0.f; zq[k] = 0.f; }
    #pragma unroll
    for (int mt = 0; mt < 4; mt++)
        #pragma unroll
        for (int nt = 0; nt < 4; nt++)
            #pragma unroll
            for (int h = 0; h < 2; h++) {
                float2 f2v = __half22float2(*(const __half2*)&c[mt][nt][h]);
                int k = mt * 2 + h;
                #pragma unroll
                for (int e = 0; e < 2; e++) {
                    float sv = (e ? f2v.y : f2v.x) * INV_QS2;
                    zl[k] += __expf(sv * INV_TEMP);
                    float q  = fmaxf(fmaf(-2.0f, sv, 2.0f), 0.0f);
                    float ev = __expf(sqrt_approx(q));
                    zd[k] += ev;
                    zq[k] = fmaf(ev, ev, zq[k]);
                }
            }
    #pragma unroll
    for (int o = 1; o <= 2; o <<= 1)
        #pragma unroll
        for (int k = 0; k < 8; k++) {
            zl[k] += __shfl_xor_sync(0xffffffffu, zl[k], o);
            zd[k] += __shfl_xor_sync(0xffffffffu, zd[k], o);
            zq[k] += __shfl_xor_sync(0xffffffffu, zq[k], o);
        }
    __syncthreads();
    float* sP = (float*)smem;  // [64 rows][4 wn][3]
    if (t == 0) {
        #pragma unroll
        for (int mt = 0; mt < 4; mt++)
            #pragma unroll
            for (int h = 0; h < 2; h++) {
                int r = mt * 16 + h * 8 + g;
                int k = mt * 2 + h;
                sP[(r * 4 + wn) * 3 + 0] = zl[k];
                sP[(r * 4 + wn) * 3 + 1] = zd[k];
                sP[(r * 4 + wn) * 3 + 2] = zq[k];
            }
    }
    __syncthreads();
    if (tid < TM) {
        float a0 = 0.f, a1 = 0.f, a2 = 0.f;
        #pragma unroll
        for (int w = 0; w < 4; w++) {
            a0 += sP[(tid * 4 + w) * 3 + 0];
            a1 += sP[(tid * 4 + w) * 3 + 1];
            a2 += sP[(tid * 4 + w) * 3 + 2];
        }
        size_t rg = (size_t)mb * TM + tid;
        g_part[(((size_t)(pair * 3 + 0) * BSZ) + rg) * NB_TILES + nb] = a0;
        g_part[(((size_t)(pair * 3 + 1) * BSZ) + rg) * NB_TILES + nb] = a1;
        g_part[(((size_t)(pair * 3 + 2) * BSZ) + rg) * NB_TILES + nb] = a2;
    }
}

// ---------------- K3: reduce per-row partials over n-tiles (contiguous) ----------------
__global__ void partred_kernel() {
    int idx = blockIdx.x * 256 + threadIdx.x;  // 9216 total
    if (idx >= 9 * BSZ) return;
    const float4* src = (const float4*)(g_part + (size_t)idx * NB_TILES);
    float a = 0.f;
    #pragma unroll
    for (int k = 0; k < NB_TILES / 4; k++) {
        float4 v = src[k];
        a += (v.x + v.y) + (v.z + v.w);
    }
    int pq = idx >> 10, row = idx & (BSZ - 1);
    int p = pq / 3, q = pq % 3;
    g_stats[((size_t)p * BSZ + row) * 3 + q] = a;
}

// ---------------- K4: S[b, target_b] fp32 dot (exact) ----------------
__global__ void dot_kernel(const float* __restrict__ f0, const float* __restrict__ f1,
                           const float* __restrict__ f2, const int* __restrict__ targets) {
    __shared__ float sm[32];
    int b = blockIdx.x, p = blockIdx.y, tid = threadIdx.x;
    const float* F = (p == 0 ? f0 : (p == 1 ? f1 : f2));
    int tg = targets[b];
    const float* xr = g_Xn + ((size_t)p * BSZ + b) * DIM;
    const float* fr = F + (size_t)tg * DIM;
    float s = 0.f;
    #pragma unroll
    for (int i = 0; i < 8; i++) s = fmaf(xr[tid + i * 256], fr[tid + i * 256], s);
    s = blockReduceSum(s, sm);
    if (tid == 0) g_st[p * BSZ + b] = s;
}

// ---------------- K5: finalize loss ----------------
__global__ void final_kernel(float* __restrict__ out) {
    __shared__ float sm[32];
    int b = threadIdx.x;
    float acc = 0.0f;
    #pragma unroll
    for (int p = 0; p < 3; p++) {
        float zl  = g_stats[((size_t)p * BSZ + b) * 3 + 0];
        float zd  = g_stats[((size_t)p * BSZ + b) * 3 + 1];
        float zq  = g_stats[((size_t)p * BSZ + b) * 3 + 2];
        float stv = g_st[p * BSZ + b];
        float ce1 = logf(zl) - stv * INV_TEMP;
        float dt  = sqrtf(fmaxf(2.0f - 2.0f * stv, 0.0f));
        float et  = expf(dt);
        float ce3 = logf((float)NMEM + 1.0f + zq / (2.0f * zd * zd)) - et / zd;
        float ldr = g_ldRow[p * BSZ + b];
        acc += 0.5f * (ce1 + ce3 + ldr);
    }
    float total = blockReduceSum(acc, sm);
    if (threadIdx.x == 0) out[0] = total * (1.0f / (float)BSZ);
}

// ---------------- launch ----------------
extern "C" void kernel_launch(void* const* d_in, const int* in_sizes, int n_in,
                              void* d_out, int out_size) {
    const float* x  = (const float*)d_in[0];
    const float* xu = (const float*)d_in[1];
    const float* xd = (const float*)d_in[2];
    const float* tx = (const float*)d_in[3];
    const float* tu = (const float*)d_in[4];
    const float* td = (const float*)d_in[5];
    const int*   tg = (const int*)d_in[6];
    const float* f0 = (const float*)d_in[8];
    const float* f1 = (const float*)d_in[9];
    const float* f2 = (const float*)d_in[10];
    float* out = (float*)d_out;

    cudaFuncSetAttribute(gemm_kernel, cudaFuncAttributeMaxDynamicSharedMemorySize, SMEM_TOTAL);

    prep_kernel  <<<dim3(2048, 3), 256>>>(x, xu, xd, tx, tu, td, f0, f1, f2);
    probe_kernel <<<1, 32>>>();
    probe2_kernel<<<1, 32>>>();   // gemm stays the 4th launch (ncu profiled slot)
    gemm_kernel  <<<dim3(BSZ / TM, NB_TILES, 3), GTHREADS, SMEM_TOTAL>>>();
    partred_kernel<<<36, 256>>>();
    dot_kernel   <<<dim3(BSZ, 3), 256>>>(f0, f1, f2, tg);
    final_kernel <<<1, 1024>>>(out);
}

// round 14
// speedup vs baseline: 1.0025x; 1.0025x over previous
#include <cuda_runtime.h>
#include <cuda_bf16.h>
#include <cuda_fp16.h>
#include <cstdint>

// Problem constants
#define BSZ 1024
#define DIM 2048
#define NMEM 16384
#define INV_TEMP 20.0f
#define QSCALE 32.0f
#define INV_QS2 (1.0f / (QSCALE * QSCALE))

// GEMM tiling (fp8). 128x128 tile, 128 threads (2x2 warps of 64x64),
// KC=64, 3 stages = 48KB/CTA -> 4 CTAs/SM.
#define TM 128
#define TN 128
#define KC 64
#define NSTG 3
#define NKIT (DIM / KC)        // 32
#define NB_TILES (NMEM / TN)   // 128
#define STAGE_BYTES ((TM + TN) * KC)    // 16384
#define SMEM_TOTAL (NSTG * STAGE_BYTES) // 49152
#define GTHREADS 128

// ---------------- scratch ----------------
__device__ uint8_t  g_Xq [3u * BSZ * DIM];
__device__ uint8_t  g_Fq [3u * (size_t)NMEM * DIM];
__device__ float    g_part[3u * 3u * (size_t)BSZ * NB_TILES];  // [pq][row][nbk]
__device__ float    g_stats[3u * BSZ * 3u];
__device__ float    g_ldRow[3u * BSZ];
__device__ float    g_st  [3u * BSZ];

// ---------------- helpers ----------------
__device__ __forceinline__ uint32_t smem_u32(const void* p) {
    uint32_t a;
    asm("{ .reg .u64 t; cvta.to.shared.u64 t, %1; cvt.u32.u64 %0, t; }" : "=r"(a) : "l"(p));
    return a;
}
__device__ __forceinline__ void cp16(uint32_t saddr, const void* g) {
    asm volatile("cp.async.cg.shared.global [%0], [%1], 16;\n" :: "r"(saddr), "l"(g));
}
__device__ __forceinline__ void cp_commit() { asm volatile("cp.async.commit_group;\n" ::: "memory"); }
__device__ __forceinline__ void cp_wait1()  { asm volatile("cp.async.wait_group 1;\n" ::: "memory"); }

__device__ __forceinline__ void ldsm4(uint32_t (&r)[4], uint32_t addr) {
    asm volatile("ldmatrix.sync.aligned.m8n8.x4.shared.b16 {%0,%1,%2,%3}, [%4];"
                 : "=r"(r[0]), "=r"(r[1]), "=r"(r[2]), "=r"(r[3]) : "r"(addr));
}
// FP8 QMMA with FP16 accumulators
__device__ __forceinline__ void mma16832h(uint32_t (&c)[2], const uint32_t (&a)[4],
                                          uint32_t b0, uint32_t b1) {
    asm volatile(
        "mma.sync.aligned.m16n8k32.row.col.f16.e4m3.e4m3.f16 "
        "{%0,%1}, {%2,%3,%4,%5}, {%6,%7}, {%0,%1};\n"
        : "+r"(c[0]), "+r"(c[1])
        : "r"(a[0]), "r"(a[1]), "r"(a[2]), "r"(a[3]), "r"(b0), "r"(b1));
}
__device__ __forceinline__ float sqrt_approx(float x) {
    float r; asm("sqrt.approx.f32 %0, %1;" : "=f"(r) : "f"(x)); return r;
}
__device__ __forceinline__ uint32_t pack_e4m3_4(float a, float b, float c, float d) {
    uint16_t lo, hi;
    asm("cvt.rn.satfinite.e4m3x2.f32 %0, %1, %2;" : "=h"(lo) : "f"(b), "f"(a));
    asm("cvt.rn.satfinite.e4m3x2.f32 %0, %1, %2;" : "=h"(hi) : "f"(d), "f"(c));
    return (uint32_t)lo | ((uint32_t)hi << 16);
}

__device__ __forceinline__ float blockReduceSum(float v, float* sm) {
    const unsigned m = 0xffffffffu;
    #pragma unroll
    for (int o = 16; o; o >>= 1) v += __shfl_down_sync(m, v, o);
    int lane = threadIdx.x & 31, w = threadIdx.x >> 5;
    __syncthreads();
    if (lane == 0) sm[w] = v;
    __syncthreads();
    if (w == 0) {
        int nw = blockDim.x >> 5;
        float r = (lane < nw) ? sm[lane] : 0.0f;
        #pragma unroll
        for (int o = 16; o; o >>= 1) r += __shfl_down_sync(m, r, o);
        if (lane == 0) sm[0] = r;
    }
    __syncthreads();
    return sm[0];
}

// ---------------- probes (keep gemm in ncu's profiled 4th-launch slot) --------
__global__ void probe_kernel() {}
__global__ void probe2_kernel() {}

// ---------------- K1: fused normalize+quantize+target-dot and fconv -----------
// gridDim = (2048, 3): x < 1024 -> norm block b=x, pair=y; x >= 1024 -> fconv slice.
__global__ void prep_kernel(const float* __restrict__ x0, const float* __restrict__ x1,
                            const float* __restrict__ x2, const float* __restrict__ t0,
                            const float* __restrict__ t1, const float* __restrict__ t2,
                            const float* __restrict__ f0, const float* __restrict__ f1,
                            const float* __restrict__ f2, const int* __restrict__ targets) {
    int p = blockIdx.y, tid = threadIdx.x;
    const float* F = (p == 0 ? f0 : (p == 1 ? f1 : f2));
    if (blockIdx.x >= 1024) {
        // ---- fconv slice ----
        int j = blockIdx.x - 1024;
        uint32_t* out = (uint32_t*)(g_Fq + (size_t)p * NMEM * DIM);
        #pragma unroll
        for (int w = 0; w < 32; w++) {
            int i = j * 256 + tid + w * (1024 * 256);
            float4 v = ((const float4*)F)[i];
            out[i] = pack_e4m3_4(v.x*QSCALE, v.y*QSCALE, v.z*QSCALE, v.w*QSCALE);
        }
        return;
    }
    // ---- norm + quantize + target dot ----
    __shared__ float sm[32];
    int b = blockIdx.x;
    const float* X = (p == 0 ? x0 : (p == 1 ? x1 : x2)) + (size_t)b * DIM;
    const float* T = (p == 0 ? t0 : (p == 1 ? t1 : t2)) + (size_t)b * DIM;
    int tg = targets[b];
    const float4* Ft = (const float4*)(F + (size_t)tg * DIM);
    float xr[8], tr[8], sx = 0.f, st = 0.f;
    #pragma unroll
    for (int gI = 0; gI < 2; gI++) {
        float4 xv = ((const float4*)X)[tid + gI * 256];
        float4 tv = ((const float4*)T)[tid + gI * 256];
        xr[gI*4+0]=xv.x; xr[gI*4+1]=xv.y; xr[gI*4+2]=xv.z; xr[gI*4+3]=xv.w;
        tr[gI*4+0]=tv.x; tr[gI*4+1]=tv.y; tr[gI*4+2]=tv.z; tr[gI*4+3]=tv.w;
        #pragma unroll
        for (int j = 0; j < 4; j++) {
            sx = fmaf(xr[gI*4+j], xr[gI*4+j], sx);
            st = fmaf(tr[gI*4+j], tr[gI*4+j], st);
        }
    }
    sx = blockReduceSum(sx, sm);
    st = blockReduceSum(st, sm);
    float ix = 1.0f / fmaxf(sqrtf(sx), 1e-12f);
    float it = 1.0f / fmaxf(sqrtf(st), 1e-12f);
    uint32_t* outq = (uint32_t*)(g_Xq + ((size_t)p * BSZ + b) * DIM);
    float ld = 0.f, dt = 0.f;
    #pragma unroll
    for (int gI = 0; gI < 2; gI++) {
        float4 fv = Ft[tid + gI * 256];
        float fr[4] = {fv.x, fv.y, fv.z, fv.w};
        float xn[4];
        #pragma unroll
        for (int j = 0; j < 4; j++) {
            xn[j] = xr[gI*4+j] * ix;
            float d = xn[j] - tr[gI*4+j] * it;
            ld = fmaf(d, d, ld);
            dt = fmaf(xn[j], fr[j], dt);
        }
        outq[tid + gI * 256] = pack_e4m3_4(xn[0]*QSCALE, xn[1]*QSCALE, xn[2]*QSCALE, xn[3]*QSCALE);
    }
    ld = blockReduceSum(ld, sm);
    dt = blockReduceSum(dt, sm);
    if (tid == 0) {
        g_ldRow[p * BSZ + b] = ld;
        g_st  [p * BSZ + b] = dt;
    }
}

// ---------------- K2: FP8 QMMA GEMM, 128x128 tile, 128 thr, 4 CTAs/SM ---------
// 64B rows; swizzle: soff = r*64 + ((c ^ ((r>>1)&3)) << 4).
__global__ void __launch_bounds__(GTHREADS, 4) gemm_kernel() {
    extern __shared__ char smem[];
    const uint32_t smem_base = smem_u32(smem);
    const int tid = threadIdx.x;
    const int wid = tid >> 5, lane = tid & 31;
    const int mb = blockIdx.x, nb = blockIdx.y, pair = blockIdx.z;  // mb fastest: co-residents share B
    const uint8_t* A  = g_Xq + ((size_t)pair * BSZ  + (size_t)mb * TM) * DIM;
    const uint8_t* Bm = g_Fq + ((size_t)pair * NMEM + (size_t)nb * TN) * DIM;

    const int wm = wid >> 1, wn = wid & 1;     // 2x2 warp grid; warp tile 64(M) x 64(N)
    const int l15 = lane & 15, hi = lane >> 4;
    const int g = lane >> 2, t = lane & 3;

    // cp.async bases: rA = tid>>2 (0..31), cA = tid&3; 32-row steps keep (r>>1)&3 -> +2048 imm.
    const uint32_t rA = (uint32_t)tid >> 2;
    const uint32_t cA = (uint32_t)tid & 3;
    const uint8_t* gA = A  + rA * DIM + cA * 16;
    const uint8_t* gB = Bm + rA * DIM + cA * 16;
    const uint32_t sA0 = (rA << 6) + (((cA ^ ((rA >> 1) & 3))) << 4);

    // ldmatrix bases; addr(ks) = base ^ (ks<<5), ks in {0,1}; mt/ng step = +1024 (16 rows).
    const uint32_t rAm = (uint32_t)(wm * 64) + l15;
    const uint32_t aBase = (rAm << 6) + ((((uint32_t)hi ^ ((rAm >> 1) & 3))) << 4);
    const uint32_t rBm = (uint32_t)(wn * 64) + l15;
    const uint32_t bBase = (uint32_t)(TM * KC) + (rBm << 6)
                         + ((((uint32_t)hi ^ ((rBm >> 1) & 3))) << 4);

    uint32_t c[4][8][2];   // f16x2 accumulators: 64(M) x 64(N) per warp
    #pragma unroll
    for (int mt = 0; mt < 4; mt++)
        #pragma unroll
        for (int nt = 0; nt < 8; nt++) { c[mt][nt][0] = 0u; c[mt][nt][1] = 0u; }

    // prologue: stages 0,1 (8 cp16/thread per stage: 4 A-row-steps + 4 B)
    #pragma unroll
    for (int j = 0; j < NSTG - 1; j++) {
        uint32_t sb = smem_base + j * STAGE_BYTES;
        #pragma unroll
        for (int w = 0; w < 4; w++)
            cp16(sb + sA0 + w * 2048, gA + j * KC + w * 32 * DIM);
        #pragma unroll
        for (int w = 0; w < 4; w++)
            cp16(sb + TM * KC + sA0 + w * 2048, gB + j * KC + w * 32 * DIM);
        cp_commit();
    }

    int s = 0, s2 = 2;   // current stage, prefetch stage (mod 3 counters)
    for (int i = 0; i < NKIT; i++) {
        const uint32_t sb = smem_base + s * STAGE_BYTES;
        cp_wait1();
        __syncthreads();   // stage i ready; stage i-1 consumed by all warps
        if (i + NSTG - 1 < NKIT) {
            uint32_t sbp = smem_base + s2 * STAGE_BYTES;
            int k0 = (i + NSTG - 1) * KC;
            #pragma unroll
            for (int w = 0; w < 4; w++)
                cp16(sbp + sA0 + w * 2048, gA + k0 + w * 32 * DIM);
            #pragma unroll
            for (int w = 0; w < 4; w++)
                cp16(sbp + TM * KC + sA0 + w * 2048, gB + k0 + w * 32 * DIM);
        }
        cp_commit();   // (possibly empty) keeps wait arithmetic uniform
        #pragma unroll
        for (int ks = 0; ks < 2; ks++) {
            uint32_t af[4][4], bfr[4][4];
            uint32_t x = (uint32_t)ks << 5;
            #pragma unroll
            for (int mt = 0; mt < 4; mt++)
                ldsm4(af[mt], (sb + aBase + mt * 1024) ^ x);
            #pragma unroll
            for (int ng = 0; ng < 4; ng++)
                ldsm4(bfr[ng], (sb + bBase + ng * 1024) ^ x);
            #pragma unroll
            for (int mt = 0; mt < 4; mt++)
                #pragma unroll
                for (int nt = 0; nt < 8; nt++) {
                    int ng = nt >> 1, od = nt & 1;
                    mma16832h(c[mt][nt], af[mt], bfr[ng][od], bfr[ng][od + 2]);
                }
        }
        s  = (s  == 2) ? 0 : s  + 1;
        s2 = (s2 == 2) ? 0 : s2 + 1;
    }

    // ---- fused epilogue: per-row partials ZL, ZD, ZD2 ----
    float zl[8], zd[8], zq[8];   // k = mt*2 + h
    #pragma unroll
    for (int k = 0; k < 8; k++) { zl[k] = 0.f; zd[k] = 0.f; zq[k] = 0.f; }
    #pragma unroll
    for (int mt = 0; mt < 4; mt++)
        #pragma unroll
        for (int nt = 0; nt < 8; nt++)
            #pragma unroll
            for (int h = 0; h < 2; h++) {
                float2 f2v = __half22float2(*(const __half2*)&c[mt][nt][h]);
                int k = mt * 2 + h;
                #pragma unroll
                for (int e = 0; e < 2; e++) {
                    float sv = (e ? f2v.y : f2v.x) * INV_QS2;
                    zl[k] += __expf(sv * INV_TEMP);
                    float q  = fmaxf(fmaf(-2.0f, sv, 2.0f), 0.0f);
                    float ev = __expf(sqrt_approx(q));
                    zd[k] += ev;
                    zq[k] = fmaf(ev, ev, zq[k]);
                }
            }
    #pragma unroll
    for (int o = 1; o <= 2; o <<= 1)
        #pragma unroll
        for (int k = 0; k < 8; k++) {
            zl[k] += __shfl_xor_sync(0xffffffffu, zl[k], o);
            zd[k] += __shfl_xor_sync(0xffffffffu, zd[k], o);
            zq[k] += __shfl_xor_sync(0xffffffffu, zq[k], o);
        }
    __syncthreads();
    float* sP = (float*)smem;  // [128 rows][2 wn][3]
    if (t == 0) {
        #pragma unroll
        for (int mt = 0; mt < 4; mt++)
            #pragma unroll
            for (int h = 0; h < 2; h++) {
                int r = wm * 64 + mt * 16 + h * 8 + g;
                int k = mt * 2 + h;
                sP[(r * 2 + wn) * 3 + 0] = zl[k];
                sP[(r * 2 + wn) * 3 + 1] = zd[k];
                sP[(r * 2 + wn) * 3 + 2] = zq[k];
            }
    }
    __syncthreads();
    if (tid < TM) {
        float a0 = sP[(tid * 2 + 0) * 3 + 0] + sP[(tid * 2 + 1) * 3 + 0];
        float a1 = sP[(tid * 2 + 0) * 3 + 1] + sP[(tid * 2 + 1) * 3 + 1];
        float a2 = sP[(tid * 2 + 0) * 3 + 2] + sP[(tid * 2 + 1) * 3 + 2];
        size_t rg = (size_t)mb * TM + tid;
        g_part[(((size_t)(pair * 3 + 0) * BSZ) + rg) * NB_TILES + nb] = a0;
        g_part[(((size_t)(pair * 3 + 1) * BSZ) + rg) * NB_TILES + nb] = a1;
        g_part[(((size_t)(pair * 3 + 2) * BSZ) + rg) * NB_TILES + nb] = a2;
    }
}

// ---------------- K3: reduce per-row partials over n-tiles (contiguous) ----------------
__global__ void partred_kernel() {
    int idx = blockIdx.x * 256 + threadIdx.x;  // 9216 total
    if (idx >= 9 * BSZ) return;
    const float4* src = (const float4*)(g_part + (size_t)idx * NB_TILES);
    float a = 0.f;
    #pragma unroll
    for (int k = 0; k < NB_TILES / 4; k++) {
        float4 v = src[k];
        a += (v.x + v.y) + (v.z + v.w);
    }
    int pq = idx >> 10, row = idx & (BSZ - 1);
    int p = pq / 3, q = pq % 3;
    g_stats[((size_t)p * BSZ + row) * 3 + q] = a;
}

// ---------------- K5: finalize loss ----------------
__global__ void final_kernel(float* __restrict__ out) {
    __shared__ float sm[32];
    int b = threadIdx.x;
    float acc = 0.0f;
    #pragma unroll
    for (int p = 0; p < 3; p++) {
        float zl  = g_stats[((size_t)p * BSZ + b) * 3 + 0];
        float zd  = g_stats[((size_t)p * BSZ + b) * 3 + 1];
        float zq  = g_stats[((size_t)p * BSZ + b) * 3 + 2];
        float stv = g_st[p * BSZ + b];
        float ce1 = logf(zl) - stv * INV_TEMP;
        float dt  = sqrtf(fmaxf(2.0f - 2.0f * stv, 0.0f));
        float et  = expf(dt);
        float ce3 = logf((float)NMEM + 1.0f + zq / (2.0f * zd * zd)) - et / zd;
        float ldr = g_ldRow[p * BSZ + b];
        acc += 0.5f * (ce1 + ce3 + ldr);
    }
    float total = blockReduceSum(acc, sm);
    if (threadIdx.x == 0) out[0] = total * (1.0f / (float)BSZ);
}

// ---------------- launch ----------------
extern "C" void kernel_launch(void* const* d_in, const int* in_sizes, int n_in,
                              void* d_out, int out_size) {
    const float* x  = (const float*)d_in[0];
    const float* xu = (const float*)d_in[1];
    const float* xd = (const float*)d_in[2];
    const float* tx = (const float*)d_in[3];
    const float* tu = (const float*)d_in[4];
    const float* td = (const float*)d_in[5];
    const int*   tg = (const int*)d_in[6];
    const float* f0 = (const float*)d_in[8];
    const float* f1 = (const float*)d_in[9];
    const float* f2 = (const float*)d_in[10];
    float* out = (float*)d_out;

    cudaFuncSetAttribute(gemm_kernel, cudaFuncAttributeMaxDynamicSharedMemorySize, SMEM_TOTAL);

    prep_kernel  <<<dim3(2048, 3), 256>>>(x, xu, xd, tx, tu, td, f0, f1, f2, tg);
    probe_kernel <<<1, 32>>>();
    probe2_kernel<<<1, 32>>>();   // gemm stays the 4th launch (ncu profiled slot)
    gemm_kernel  <<<dim3(BSZ / TM, NB_TILES, 3), GTHREADS, SMEM_TOTAL>>>();
    partred_kernel<<<36, 256>>>();
    final_kernel <<<1, 1024>>>(out);
}

// round 15
// speedup vs baseline: 1.0244x; 1.0219x over previous
#include <cuda_runtime.h>
#include <cuda_bf16.h>
#include <cuda_fp16.h>
#include <cstdint>

// Problem constants
#define BSZ 1024
#define DIM 2048
#define NMEM 16384
#define INV_TEMP 20.0f
#define QSCALE 32.0f
#define INV_QS2 (1.0f / (QSCALE * QSCALE))

// GEMM tiling (fp8). 128x128 tile, KC=128, 2 stages = 64KB/CTA -> 3 CTAs/SM (R12 config).
#define TM 128
#define TN 128
#define KC 128
#define NSTG 2
#define NKIT (DIM / KC)        // 16
#define NB_TILES (NMEM / TN)   // 128
#define STAGE_BYTES ((TM + TN) * KC)    // 32768
#define SMEM_TOTAL (NSTG * STAGE_BYTES) // 65536
#define GTHREADS 256

// ---------------- scratch ----------------
__device__ uint8_t  g_Xq [3u * BSZ * DIM];
__device__ uint8_t  g_Fq [3u * (size_t)NMEM * DIM];
__device__ float    g_part[3u * 3u * (size_t)BSZ * NB_TILES];  // [pq][row][nbk]
__device__ float    g_stats[3u * BSZ * 3u];
__device__ float    g_ldRow[3u * BSZ];
__device__ float    g_st  [3u * BSZ];

// ---------------- helpers ----------------
__device__ __forceinline__ uint32_t smem_u32(const void* p) {
    uint32_t a;
    asm("{ .reg .u64 t; cvta.to.shared.u64 t, %1; cvt.u32.u64 %0, t; }" : "=r"(a) : "l"(p));
    return a;
}
__device__ __forceinline__ void cp16(uint32_t saddr, const void* g) {
    asm volatile("cp.async.cg.shared.global [%0], [%1], 16;\n" :: "r"(saddr), "l"(g));
}
__device__ __forceinline__ void cp_commit() { asm volatile("cp.async.commit_group;\n" ::: "memory"); }
__device__ __forceinline__ void cp_wait1()  { asm volatile("cp.async.wait_group 1;\n" ::: "memory"); }

__device__ __forceinline__ void ldsm4(uint32_t (&r)[4], uint32_t addr) {
    asm volatile("ldmatrix.sync.aligned.m8n8.x4.shared.b16 {%0,%1,%2,%3}, [%4];"
                 : "=r"(r[0]), "=r"(r[1]), "=r"(r[2]), "=r"(r[3]) : "r"(addr));
}
// FP8 QMMA with FP16 accumulators
__device__ __forceinline__ void mma16832h(uint32_t (&c)[2], const uint32_t (&a)[4],
                                          uint32_t b0, uint32_t b1) {
    asm volatile(
        "mma.sync.aligned.m16n8k32.row.col.f16.e4m3.e4m3.f16 "
        "{%0,%1}, {%2,%3,%4,%5}, {%6,%7}, {%0,%1};\n"
        : "+r"(c[0]), "+r"(c[1])
        : "r"(a[0]), "r"(a[1]), "r"(a[2]), "r"(a[3]), "r"(b0), "r"(b1));
}
__device__ __forceinline__ float sqrt_approx(float x) {
    float r; asm("sqrt.approx.f32 %0, %1;" : "=f"(r) : "f"(x)); return r;
}
__device__ __forceinline__ uint32_t pack_e4m3_4(float a, float b, float c, float d) {
    uint16_t lo, hi;
    asm("cvt.rn.satfinite.e4m3x2.f32 %0, %1, %2;" : "=h"(lo) : "f"(b), "f"(a));
    asm("cvt.rn.satfinite.e4m3x2.f32 %0, %1, %2;" : "=h"(hi) : "f"(d), "f"(c));
    return (uint32_t)lo | ((uint32_t)hi << 16);
}

__device__ __forceinline__ float blockReduceSum(float v, float* sm) {
    const unsigned m = 0xffffffffu;
    #pragma unroll
    for (int o = 16; o; o >>= 1) v += __shfl_down_sync(m, v, o);
    int lane = threadIdx.x & 31, w = threadIdx.x >> 5;
    __syncthreads();
    if (lane == 0) sm[w] = v;
    __syncthreads();
    if (w == 0) {
        int nw = blockDim.x >> 5;
        float r = (lane < nw) ? sm[lane] : 0.0f;
        #pragma unroll
        for (int o = 16; o; o >>= 1) r += __shfl_down_sync(m, r, o);
        if (lane == 0) sm[0] = r;
    }
    __syncthreads();
    return sm[0];
}

// ---------------- probes (keep gemm in ncu's profiled 4th-launch slot) --------
__global__ void probe_kernel() {}
__global__ void probe2_kernel() {}

// ---------------- K1: fused normalize+quantize+target-dot and fconv -----------
// gridDim = (2048, 3): x < 1024 -> norm block b=x, pair=y; x >= 1024 -> fconv slice.
__global__ void prep_kernel(const float* __restrict__ x0, const float* __restrict__ x1,
                            const float* __restrict__ x2, const float* __restrict__ t0,
                            const float* __restrict__ t1, const float* __restrict__ t2,
                            const float* __restrict__ f0, const float* __restrict__ f1,
                            const float* __restrict__ f2, const int* __restrict__ targets) {
    int p = blockIdx.y, tid = threadIdx.x;
    const float* F = (p == 0 ? f0 : (p == 1 ? f1 : f2));
    if (blockIdx.x >= 1024) {
        // ---- fconv slice ----
        int j = blockIdx.x - 1024;
        uint32_t* out = (uint32_t*)(g_Fq + (size_t)p * NMEM * DIM);
        #pragma unroll
        for (int w = 0; w < 32; w++) {
            int i = j * 256 + tid + w * (1024 * 256);
            float4 v = ((const float4*)F)[i];
            out[i] = pack_e4m3_4(v.x*QSCALE, v.y*QSCALE, v.z*QSCALE, v.w*QSCALE);
        }
        return;
    }
    // ---- norm + quantize + target dot ----
    __shared__ float sm[32];
    int b = blockIdx.x;
    const float* X = (p == 0 ? x0 : (p == 1 ? x1 : x2)) + (size_t)b * DIM;
    const float* T = (p == 0 ? t0 : (p == 1 ? t1 : t2)) + (size_t)b * DIM;
    int tg = targets[b];
    const float4* Ft = (const float4*)(F + (size_t)tg * DIM);
    float xr[8], tr[8], sx = 0.f, st = 0.f;
    #pragma unroll
    for (int gI = 0; gI < 2; gI++) {
        float4 xv = ((const float4*)X)[tid + gI * 256];
        float4 tv = ((const float4*)T)[tid + gI * 256];
        xr[gI*4+0]=xv.x; xr[gI*4+1]=xv.y; xr[gI*4+2]=xv.z; xr[gI*4+3]=xv.w;
        tr[gI*4+0]=tv.x; tr[gI*4+1]=tv.y; tr[gI*4+2]=tv.z; tr[gI*4+3]=tv.w;
        #pragma unroll
        for (int j = 0; j < 4; j++) {
            sx = fmaf(xr[gI*4+j], xr[gI*4+j], sx);
            st = fmaf(tr[gI*4+j], tr[gI*4+j], st);
        }
    }
    sx = blockReduceSum(sx, sm);
    st = blockReduceSum(st, sm);
    float ix = 1.0f / fmaxf(sqrtf(sx), 1e-12f);
    float it = 1.0f / fmaxf(sqrtf(st), 1e-12f);
    uint32_t* outq = (uint32_t*)(g_Xq + ((size_t)p * BSZ + b) * DIM);
    float ld = 0.f, dt = 0.f;
    #pragma unroll
    for (int gI = 0; gI < 2; gI++) {
        float4 fv = Ft[tid + gI * 256];
        float fr[4] = {fv.x, fv.y, fv.z, fv.w};
        float xn[4];
        #pragma unroll
        for (int j = 0; j < 4; j++) {
            xn[j] = xr[gI*4+j] * ix;
            float d = xn[j] - tr[gI*4+j] * it;
            ld = fmaf(d, d, ld);
            dt = fmaf(xn[j], fr[j], dt);
        }
        outq[tid + gI * 256] = pack_e4m3_4(xn[0]*QSCALE, xn[1]*QSCALE, xn[2]*QSCALE, xn[3]*QSCALE);
    }
    ld = blockReduceSum(ld, sm);
    dt = blockReduceSum(dt, sm);
    if (tid == 0) {
        g_ldRow[p * BSZ + b] = ld;
        g_st  [p * BSZ + b] = dt;
    }
}

// ---------------- K2: FP8 QMMA GEMM, 128x128 tile, 256 thr, 3 CTAs/SM (R12) ---
__global__ void __launch_bounds__(GTHREADS, 3) gemm_kernel() {
    extern __shared__ char smem[];
    const uint32_t smem_base = smem_u32(smem);
    const int tid = threadIdx.x;
    const int wid = tid >> 5, lane = tid & 31;
    const int mb = blockIdx.x, nb = blockIdx.y, pair = blockIdx.z;  // mb fastest: co-residents share B
    const uint8_t* A  = g_Xq + ((size_t)pair * BSZ  + (size_t)mb * TM) * DIM;
    const uint8_t* Bm = g_Fq + ((size_t)pair * NMEM + (size_t)nb * TN) * DIM;

    const int wm = wid >> 2, wn = wid & 3;     // 2x4 warp grid; warp tile 64(M) x 32(N)
    const int l15 = lane & 15, hi = lane >> 4;
    const int g = lane >> 2, t = lane & 3;

    // cp.async bases: rA = tid>>3 (0..31), chA = tid&7; 32-row steps keep r&7.
    const uint32_t rA  = (uint32_t)tid >> 3;
    const uint32_t chA = (uint32_t)tid & 7;
    const uint8_t* gA = A  + rA * DIM + chA * 16;
    const uint8_t* gB = Bm + rA * DIM + chA * 16;
    const uint32_t sA0 = (rA << 7) + (((chA ^ (rA & 7))) << 4);

    // ldmatrix bases; addr(ks) = base ^ (ks<<5), ks 0..3; mt/ng step = +2048 (16 rows)
    const uint32_t rAm = (uint32_t)(wm * 64) + l15;
    const uint32_t aBase = (rAm << 7) + ((((uint32_t)hi ^ (rAm & 7))) << 4);
    const uint32_t rBm = (uint32_t)(wn * 32) + l15;
    const uint32_t bBase = (uint32_t)(TM * KC) + (rBm << 7) + ((((uint32_t)hi ^ (rBm & 7))) << 4);

    uint32_t c[4][4][2];   // f16x2 accumulators: 64(M) x 32(N) per warp
    #pragma unroll
    for (int mt = 0; mt < 4; mt++)
        #pragma unroll
        for (int nt = 0; nt < 4; nt++) { c[mt][nt][0] = 0u; c[mt][nt][1] = 0u; }

    // prologue: both stages (8 cp16/thread per stage: 4 A-rows-steps + 4 B)
    #pragma unroll
    for (int j = 0; j < 2; j++) {
        uint32_t sb = smem_base + j * STAGE_BYTES;
        #pragma unroll
        for (int w = 0; w < 4; w++)
            cp16(sb + sA0 + w * 4096, gA + j * KC + w * 32 * DIM);
        #pragma unroll
        for (int w = 0; w < 4; w++)
            cp16(sb + TM * KC + sA0 + w * 4096, gB + j * KC + w * 32 * DIM);
        cp_commit();
    }

    for (int i = 0; i < NKIT; i++) {
        const uint32_t sb = smem_base + (i & 1) * STAGE_BYTES;
        cp_wait1();
        __syncthreads();
        #pragma unroll
        for (int ks = 0; ks < 4; ks++) {
            uint32_t af[4][4], bfr[2][4];
            uint32_t x = (uint32_t)ks << 5;
            #pragma unroll
            for (int mt = 0; mt < 4; mt++)
                ldsm4(af[mt], (sb + aBase + mt * 2048) ^ x);
            #pragma unroll
            for (int ng = 0; ng < 2; ng++)
                ldsm4(bfr[ng], (sb + bBase + ng * 2048) ^ x);
            #pragma unroll
            for (int mt = 0; mt < 4; mt++)
                #pragma unroll
                for (int nt = 0; nt < 4; nt++) {
                    int ng = nt >> 1, od = nt & 1;
                    mma16832h(c[mt][nt], af[mt], bfr[ng][od], bfr[ng][od + 2]);
                }
        }
        __syncthreads();  // stage fully consumed before overwrite
        if (i + NSTG < NKIT) {
            int k0 = (i + NSTG) * KC;
            #pragma unroll
            for (int w = 0; w < 4; w++)
                cp16(sb + sA0 + w * 4096, gA + k0 + w * 32 * DIM);
            #pragma unroll
            for (int w = 0; w < 4; w++)
                cp16(sb + TM * KC + sA0 + w * 4096, gB + k0 + w * 32 * DIM);
        }
        cp_commit();   // (possibly empty) group keeps wait arithmetic uniform
    }

    // ---- fused epilogue: per-row partials ZL, ZD, ZD2 ----
    float zl[8], zd[8], zq[8];   // k = mt*2 + h
    #pragma unroll
    for (int k = 0; k < 8; k++) { zl[k] = 0.f; zd[k] = 0.f; zq[k] = 0.f; }
    #pragma unroll
    for (int mt = 0; mt < 4; mt++)
        #pragma unroll
        for (int nt = 0; nt < 4; nt++)
            #pragma unroll
            for (int h = 0; h < 2; h++) {
                float2 f2v = __half22float2(*(const __half2*)&c[mt][nt][h]);
                int k = mt * 2 + h;
                #pragma unroll
                for (int e = 0; e < 2; e++) {
                    float sv = (e ? f2v.y : f2v.x) * INV_QS2;
                    zl[k] += __expf(sv * INV_TEMP);
                    float q  = fmaxf(fmaf(-2.0f, sv, 2.0f), 0.0f);
                    float ev = __expf(sqrt_approx(q));
                    zd[k] += ev;
                    zq[k] = fmaf(ev, ev, zq[k]);
                }
            }
    #pragma unroll
    for (int o = 1; o <= 2; o <<= 1)
        #pragma unroll
        for (int k = 0; k < 8; k++) {
            zl[k] += __shfl_xor_sync(0xffffffffu, zl[k], o);
            zd[k] += __shfl_xor_sync(0xffffffffu, zd[k], o);
            zq[k] += __shfl_xor_sync(0xffffffffu, zq[k], o);
        }
    __syncthreads();
    float* sP = (float*)smem;  // [128 rows][4 wn][3]
    if (t == 0) {
        #pragma unroll
        for (int mt = 0; mt < 4; mt++)
            #pragma unroll
            for (int h = 0; h < 2; h++) {
                int r = wm * 64 + mt * 16 + h * 8 + g;
                int k = mt * 2 + h;
                sP[(r * 4 + wn) * 3 + 0] = zl[k];
                sP[(r * 4 + wn) * 3 + 1] = zd[k];
                sP[(r * 4 + wn) * 3 + 2] = zq[k];
            }
    }
    __syncthreads();
    if (tid < TM) {
        float a0 = 0.f, a1 = 0.f, a2 = 0.f;
        #pragma unroll
        for (int w = 0; w < 4; w++) {
            a0 += sP[(tid * 4 + w) * 3 + 0];
            a1 += sP[(tid * 4 + w) * 3 + 1];
            a2 += sP[(tid * 4 + w) * 3 + 2];
        }
        size_t rg = (size_t)mb * TM + tid;
        g_part[(((size_t)(pair * 3 + 0) * BSZ) + rg) * NB_TILES + nb] = a0;
        g_part[(((size_t)(pair * 3 + 1) * BSZ) + rg) * NB_TILES + nb] = a1;
        g_part[(((size_t)(pair * 3 + 2) * BSZ) + rg) * NB_TILES + nb] = a2;
    }
}

// ---------------- K3: reduce per-row partials over n-tiles (contiguous) ----------------
__global__ void partred_kernel() {
    int idx = blockIdx.x * 256 + threadIdx.x;  // 9216 total
    if (idx >= 9 * BSZ) return;
    const float4* src = (const float4*)(g_part + (size_t)idx * NB_TILES);
    float a = 0.f;
    #pragma unroll
    for (int k = 0; k < NB_TILES / 4; k++) {
        float4 v = src[k];
        a += (v.x + v.y) + (v.z + v.w);
    }
    int pq = idx >> 10, row = idx & (BSZ - 1);
    int p = pq / 3, q = pq % 3;
    g_stats[((size_t)p * BSZ + row) * 3 + q] = a;
}

// ---------------- K5: finalize loss ----------------
__global__ void final_kernel(float* __restrict__ out) {
    __shared__ float sm[32];
    int b = threadIdx.x;
    float acc = 0.0f;
    #pragma unroll
    for (int p = 0; p < 3; p++) {
        float zl  = g_stats[((size_t)p * BSZ + b) * 3 + 0];
        float zd  = g_stats[((size_t)p * BSZ + b) * 3 + 1];
        float zq  = g_stats[((size_t)p * BSZ + b) * 3 + 2];
        float stv = g_st[p * BSZ + b];
        float ce1 = logf(zl) - stv * INV_TEMP;
        float dt  = sqrtf(fmaxf(2.0f - 2.0f * stv, 0.0f));
        float et  = expf(dt);
        float ce3 = logf((float)NMEM + 1.0f + zq / (2.0f * zd * zd)) - et / zd;
        float ldr = g_ldRow[p * BSZ + b];
        acc += 0.5f * (ce1 + ce3 + ldr);
    }
    float total = blockReduceSum(acc, sm);
    if (threadIdx.x == 0) out[0] = total * (1.0f / (float)BSZ);
}

// ---------------- launch ----------------
extern "C" void kernel_launch(void* const* d_in, const int* in_sizes, int n_in,
                              void* d_out, int out_size) {
    const float* x  = (const float*)d_in[0];
    const float* xu = (const float*)d_in[1];
    const float* xd = (const float*)d_in[2];
    const float* tx = (const float*)d_in[3];
    const float* tu = (const float*)d_in[4];
    const float* td = (const float*)d_in[5];
    const int*   tg = (const int*)d_in[6];
    const float* f0 = (const float*)d_in[8];
    const float* f1 = (const float*)d_in[9];
    const float* f2 = (const float*)d_in[10];
    float* out = (float*)d_out;

    cudaFuncSetAttribute(gemm_kernel, cudaFuncAttributeMaxDynamicSharedMemorySize, SMEM_TOTAL);

    prep_kernel  <<<dim3(2048, 3), 256>>>(x, xu, xd, tx, tu, td, f0, f1, f2, tg);
    probe_kernel <<<1, 32>>>();
    probe2_kernel<<<1, 32>>>();   // gemm stays the 4th launch (ncu profiled slot)
    gemm_kernel  <<<dim3(BSZ / TM, NB_TILES, 3), GTHREADS, SMEM_TOTAL>>>();
    partred_kernel<<<36, 256>>>();
    final_kernel <<<1, 1024>>>(out);
}